// round 14
// baseline (speedup 1.0000x reference)
#include <cuda_runtime.h>
#include <cuda_bf16.h>
#include <cstdint>

// ---------------------------------------------------------------------------
// DLSTMCell (sm_103 baseline ISA — no tcgen05; mma.sync bf16 HMMA path)
//   Kernel 1 (hyper): W_n = mem2_n @ w3 + b3 ->
//     g_Wk[n]: bf16 [256(o', permuted) x 64(k)] SW128-swizzled smem image (32KB)
//     g_Wx[n]: fp32 input-rows i=0,1, stored at permuted columns [2*256]
//   Kernel 2 (cell): per-node D[128,256] = Hbf16[128,64] @ Wk^T via
//     mma.sync.m16n8k16 + fp32 rank-2 input correction + fused LSTM epilogue.
//   Column permutation o' = (ru>>4)*64 + gate*16 + (ru&15) puts all 4 gates of
//   a ru-group into one warp's 64-col stripe -> lane-local LSTM combine.
// ---------------------------------------------------------------------------

#define BATCH 128
#define NNODE 512
#define RUNIT 64
#define HXW   32768          // N*RU
#define W3W   16896

__device__ __align__(16) uint4 g_Wk[NNODE][2048];   // 32KB/node swizzled bf16 image
__device__ float g_Wx[NNODE][512];                  // [n][i*256+o'], i in {0,1}

// ------------------------------ helpers -----------------------------------
__device__ __forceinline__ uint32_t smem_u32(const void* p) {
    uint32_t a;
    asm("{ .reg .u64 t; cvta.to.shared.u64 t, %1; cvt.u32.u64 %0, t; }"
        : "=r"(a) : "l"(p));
    return a;
}
__device__ __forceinline__ uint32_t sw128(uint32_t off) {
    return off ^ ((off >> 3) & 0x70u);
}
__device__ __forceinline__ float tanh_ap(float x) {
    float y; asm("tanh.approx.f32 %0, %1;" : "=f"(y) : "f"(x)); return y;
}
__device__ __forceinline__ float sig_ap(float x) {   // outer sigmoid (approx)
    return fmaf(tanh_ap(0.5f * x), 0.5f, 0.5f);
}
__device__ __forceinline__ float ex2_(float x) {
    float y; asm("ex2.approx.f32 %0, %1;" : "=f"(y) : "f"(x)); return y;
}
__device__ __forceinline__ float rcp_(float x) {
    float y; asm("rcp.approx.f32 %0, %1;" : "=f"(y) : "f"(x)); return y;
}
__device__ __forceinline__ float sigf(float x) {     // accurate sigmoid
    return rcp_(1.0f + ex2_(-1.44269504f * x));
}
__device__ __forceinline__ float tanhf_(float x) {   // accurate tanh
    return fmaf(2.0f, sigf(2.0f * x), -1.0f);
}
__device__ __forceinline__ uint32_t pack_bf2(float a, float b) {
    __nv_bfloat162 h = __floats2bfloat162_rn(a, b);
    return *reinterpret_cast<uint32_t*>(&h);
}
__device__ __forceinline__ int perm256(int o) {      // gate-interleave permutation
    int g = o >> 6, ru = o & 63;
    return ((ru >> 4) << 6) + (g << 4) + (ru & 15);
}
__device__ __forceinline__ void ldsm4(uint32_t& r0, uint32_t& r1,
                                      uint32_t& r2, uint32_t& r3, uint32_t addr) {
    asm volatile("ldmatrix.sync.aligned.m8n8.x4.shared.b16 {%0,%1,%2,%3}, [%4];"
                 : "=r"(r0), "=r"(r1), "=r"(r2), "=r"(r3) : "r"(addr));
}
__device__ __forceinline__ void mma16816(float* d, const uint32_t* a,
                                         uint32_t b0, uint32_t b1) {
    asm volatile(
        "mma.sync.aligned.m16n8k16.row.col.f32.bf16.bf16.f32 "
        "{%0,%1,%2,%3}, {%4,%5,%6,%7}, {%8,%9}, {%0,%1,%2,%3};"
        : "+f"(d[0]), "+f"(d[1]), "+f"(d[2]), "+f"(d[3])
        : "r"(a[0]), "r"(a[1]), "r"(a[2]), "r"(a[3]), "r"(b0), "r"(b1));
}

// ---------------------------------------------------------------------------
// Kernel 1: hypernetwork. 4 nodes per CTA share the w3/b3 reads.
// grid = 128, block = 256, dyn smem = 4 * 32KB image staging.
// ---------------------------------------------------------------------------
__global__ void __launch_bounds__(256) hyper_kernel(
    const float* __restrict__ mem, const float* __restrict__ w1,
    const float* __restrict__ b1,  const float* __restrict__ w2,
    const float* __restrict__ b2,  const float* __restrict__ w3,
    const float* __restrict__ b3)
{
    extern __shared__ unsigned char hsm[];   // 4 * 32768 bytes
    __shared__ float s_m1[4][16];
    __shared__ float s_m2[4][4];

    const int t  = threadIdx.x;
    const int n0 = blockIdx.x * 4;
    const uint32_t hbase = smem_u32(hsm);

    if (t < 64) {
        int q = t >> 4, j = t & 15;
        float acc = b1[j];
        #pragma unroll
        for (int k = 0; k < 16; k++)
            acc = fmaf(mem[(n0 + q) * 16 + k], w1[k * 16 + j], acc);
        s_m1[q][j] = tanhf(acc);
    }
    __syncthreads();
    if (t < 16) {
        int q = t >> 2, j = t & 3;
        float acc = b2[j];
        #pragma unroll
        for (int k = 0; k < 16; k++)
            acc = fmaf(s_m1[q][k], w2[k * 4 + j], acc);
        s_m2[q][j] = tanhf(acc);
    }
    __syncthreads();

    float m[4][4];
    #pragma unroll
    for (int q = 0; q < 4; q++)
        #pragma unroll
        for (int mm = 0; mm < 4; mm++) m[q][mm] = s_m2[q][mm];

    const int o  = t;                 // original output column 0..255
    const int op = perm256(o);        // permuted storage column

    // hidden rows i = 2..65 -> bf16 swizzled image, row op (128B), col k
    #pragma unroll 1
    for (int kc = 0; kc < 8; kc++) {          // 16B chunk = 8 k's
        uint32_t pk[4][4];
        #pragma unroll
        for (int k2 = 0; k2 < 4; k2++) {      // bf16 pairs within chunk
            float v[4][2];
            #pragma unroll
            for (int s = 0; s < 2; s++) {
                int k   = kc * 8 + k2 * 2 + s;
                int idx = (k + 2) * 256 + o;
                float a0 = w3[idx];
                float a1 = w3[W3W + idx];
                float a2 = w3[2 * W3W + idx];
                float a3 = w3[3 * W3W + idx];
                float bb = b3[idx];
                #pragma unroll
                for (int q = 0; q < 4; q++) {
                    float vv = bb;
                    vv = fmaf(m[q][0], a0, vv); vv = fmaf(m[q][1], a1, vv);
                    vv = fmaf(m[q][2], a2, vv); vv = fmaf(m[q][3], a3, vv);
                    v[q][s] = vv;
                }
            }
            #pragma unroll
            for (int q = 0; q < 4; q++) pk[q][k2] = pack_bf2(v[q][0], v[q][1]);
        }
        uint32_t sw = sw128((uint32_t)op * 128u + (uint32_t)kc * 16u);
        #pragma unroll
        for (int q = 0; q < 4; q++)
            asm volatile("st.shared.v4.b32 [%0], {%1, %2, %3, %4};"
                         :: "r"(hbase + q * 32768u + sw),
                            "r"(pk[q][0]), "r"(pk[q][1]), "r"(pk[q][2]), "r"(pk[q][3])
                         : "memory");
    }
    // input rows i = 0..1 -> fp32 g_Wx at permuted column
    #pragma unroll
    for (int i = 0; i < 2; i++) {
        int idx = i * 256 + o;
        float a0 = w3[idx];
        float a1 = w3[W3W + idx];
        float a2 = w3[2 * W3W + idx];
        float a3 = w3[3 * W3W + idx];
        float bb = b3[idx];
        #pragma unroll
        for (int q = 0; q < 4; q++) {
            float v = bb;
            v = fmaf(m[q][0], a0, v); v = fmaf(m[q][1], a1, v);
            v = fmaf(m[q][2], a2, v); v = fmaf(m[q][3], a3, v);
            g_Wx[n0 + q][i * 256 + op] = v;
        }
    }
    __syncthreads();
    // flush swizzled images to gmem (coalesced uint4)
    const uint4* src = (const uint4*)hsm;
    #pragma unroll
    for (int q = 0; q < 4; q++)
        #pragma unroll
        for (int j = 0; j < 8; j++)
            g_Wk[n0 + q][j * 256 + t] = src[q * 2048 + j * 256 + t];
}

// ---------------------------------------------------------------------------
// Kernel 2: per-node HMMA GEMM + LSTM epilogue.
// grid = 512 (one node/CTA), block = 512 (16 warps: mi=w>>2 row-stripe of 32,
// nb=w&3 -> 64 permuted cols = 4 gates x 16 ru). SMEM (1024-aligned base sb):
//   [sb        , +16384) A: 128 x 128B (64 bf16), SW128
//   [sb + 16384, +32768) B: 256 x 128B (64 bf16), SW128 (copied image)
//   [sb + 49152, +2048 ) Wx (512 fp32, permuted cols)
//   [sb + 51200, +1024 ) b_out (256 fp32, permuted)
//   [sb + 52224, +1024 ) XV (x0,x1 per batch row)
// ---------------------------------------------------------------------------
__global__ void __launch_bounds__(512) cell_kernel(
    const float* __restrict__ inputs, const float* __restrict__ hx,
    const float* __restrict__ cx,     const float* __restrict__ b_out,
    float* __restrict__ out)
{
    extern __shared__ unsigned char dsm[];
    const uint32_t raw = smem_u32(dsm);
    const uint32_t sb  = (raw + 1023u) & ~1023u;
    const uint32_t pad = sb - raw;
    const uint32_t A_s = sb;
    const uint32_t B_s = sb + 16384;
    float* WXs = (float*)(dsm + pad + 49152);
    float* BOs = (float*)(dsm + pad + 51200);
    float* XVs = (float*)(dsm + pad + 52224);

    const int n   = blockIdx.x;
    const int tid = threadIdx.x;

    // ---- A tile: hx rows -> bf16, SW128. thread: row=tid>>2, quarter=tid&3 ----
    {
        int row = tid >> 2, cq = tid & 3;
        const float4* hp = (const float4*)(hx + (size_t)row * HXW + n * RUNIT + cq * 16);
        float4 p0 = hp[0], p1 = hp[1], p2 = hp[2], p3 = hp[3];
        uint32_t u0 = pack_bf2(p0.x, p0.y), u1 = pack_bf2(p0.z, p0.w);
        uint32_t u2 = pack_bf2(p1.x, p1.y), u3 = pack_bf2(p1.z, p1.w);
        uint32_t u4 = pack_bf2(p2.x, p2.y), u5 = pack_bf2(p2.z, p2.w);
        uint32_t u6 = pack_bf2(p3.x, p3.y), u7 = pack_bf2(p3.z, p3.w);
        uint32_t off = (uint32_t)row * 128u + (uint32_t)cq * 32u;
        asm volatile("st.shared.v4.b32 [%0], {%1, %2, %3, %4};"
                     :: "r"(A_s + sw128(off)), "r"(u0), "r"(u1), "r"(u2), "r"(u3) : "memory");
        asm volatile("st.shared.v4.b32 [%0], {%1, %2, %3, %4};"
                     :: "r"(A_s + sw128(off + 16)), "r"(u4), "r"(u5), "r"(u6), "r"(u7) : "memory");
    }
    // ---- B tile: copy pre-swizzled image (32KB, coalesced) ----
    {
        const uint4* src = g_Wk[n];
        #pragma unroll
        for (int j = 0; j < 4; j++) {
            uint4 v = __ldg(&src[j * 512 + tid]);
            asm volatile("st.shared.v4.b32 [%0], {%1, %2, %3, %4};"
                         :: "r"(B_s + (uint32_t)(j * 512 + tid) * 16u),
                            "r"(v.x), "r"(v.y), "r"(v.z), "r"(v.w) : "memory");
        }
    }
    // ---- Wx / b_out / x values ----
    WXs[tid] = g_Wx[n][tid];
    if (tid < 256) {
        BOs[perm256(tid)] = b_out[tid];
        XVs[tid] = inputs[(size_t)(tid >> 1) * 1024 + n * 2 + (tid & 1)];
    }
    __syncthreads();

    // ---- MMA: warp (mi,nb): rows [32mi,32mi+32) x cols [64nb,64nb+64) ----
    const int w  = tid >> 5, l = tid & 31;
    const int mi = w >> 2,  nb = w & 3;

    float acc[2][8][4];
    #pragma unroll
    for (int mt = 0; mt < 2; mt++)
        #pragma unroll
        for (int nt = 0; nt < 8; nt++)
            #pragma unroll
            for (int e = 0; e < 4; e++) acc[mt][nt][e] = 0.0f;

    #pragma unroll
    for (int ks = 0; ks < 4; ks++) {
        uint32_t a[2][4];
        #pragma unroll
        for (int mt = 0; mt < 2; mt++) {
            uint32_t row = (uint32_t)(mi * 32 + mt * 16 + (l & 15));
            uint32_t kc  = (uint32_t)(ks * 2 + (l >> 4));
            ldsm4(a[mt][0], a[mt][1], a[mt][2], a[mt][3],
                  A_s + sw128(row * 128u + kc * 16u));
        }
        uint32_t b[8][2];
        #pragma unroll
        for (int p = 0; p < 4; p++) {
            uint32_t row = (uint32_t)(nb * 64 + p * 16 + (l & 7) + ((l >> 4) << 3));
            uint32_t kc  = (uint32_t)(ks * 2 + ((l >> 3) & 1));
            ldsm4(b[2 * p][0], b[2 * p][1], b[2 * p + 1][0], b[2 * p + 1][1],
                  B_s + sw128(row * 128u + kc * 16u));
        }
        #pragma unroll
        for (int mt = 0; mt < 2; mt++)
            #pragma unroll
            for (int nt = 0; nt < 8; nt++)
                mma16816(acc[mt][nt], a[mt], b[nt][0], b[nt][1]);
    }

    // ---- LSTM epilogue: lane-local gate combine ----
    const int qrow  = l >> 2;
    const int qc    = (l & 3) << 1;
    const int nbase = n * RUNIT + nb * 16;

    #pragma unroll
    for (int ruhi = 0; ruhi < 2; ruhi++) {
        float wx0[2][4], wx1[2][4], bov[2][4];
        #pragma unroll
        for (int c = 0; c < 2; c++) {
            int o0 = nb * 64 + ruhi * 8 + qc + c;   // permuted col, gate stride 16
            #pragma unroll
            for (int g = 0; g < 4; g++) {
                wx0[c][g] = WXs[o0 + g * 16];
                wx1[c][g] = WXs[256 + o0 + g * 16];
                bov[c][g] = BOs[o0 + g * 16];
            }
        }
        #pragma unroll
        for (int mt = 0; mt < 2; mt++) {
            #pragma unroll
            for (int h = 0; h < 2; h++) {
                int row = mi * 32 + mt * 16 + h * 8 + qrow;
                float x0 = XVs[2 * row], x1 = XVs[2 * row + 1];
                size_t goff = (size_t)row * HXW + nbase + ruhi * 8 + qc;
                float2 cx2 = *(const float2*)(cx + goff);
                float2 hy2, cy2;
                #pragma unroll
                for (int c = 0; c < 2; c++) {
                    int e = h * 2 + c;
                    float li = fmaf(x1, wx1[c][0], fmaf(x0, wx0[c][0], acc[mt][0 + ruhi][e]));
                    float lf = fmaf(x1, wx1[c][1], fmaf(x0, wx0[c][1], acc[mt][2 + ruhi][e]));
                    float lg = fmaf(x1, wx1[c][2], fmaf(x0, wx0[c][2], acc[mt][4 + ruhi][e]));
                    float lo = fmaf(x1, wx1[c][3], fmaf(x0, wx0[c][3], acc[mt][6 + ruhi][e]));
                    float vi = sig_ap(li) + bov[c][0];
                    float vf = sig_ap(lf) + bov[c][1];
                    float vg = sig_ap(lg) + bov[c][2];
                    float vo = sig_ap(lo) + bov[c][3];
                    float it = sigf(vi);
                    float ft = sigf(vf);
                    float gt = tanhf_(vg);
                    float ot = sigf(vo);
                    float cxv = c ? cx2.y : cx2.x;
                    float cc = fmaf(cxv, ft, it * gt);
                    float hh = ot * tanhf_(cc);
                    if (c == 0) { cy2.x = cc; hy2.x = hh; }
                    else        { cy2.y = cc; hy2.y = hh; }
                }
                *(float2*)(out + goff) = hy2;
                *(float2*)(out + (size_t)BATCH * HXW + goff) = cy2;
            }
        }
    }
}

// ---------------------------------------------------------------------------
extern "C" void kernel_launch(void* const* d_in, const int* in_sizes, int n_in,
                              void* d_out, int out_size)
{
    (void)in_sizes; (void)n_in; (void)out_size;
    const float* inputs = (const float*)d_in[0];
    const float* hx     = (const float*)d_in[1];
    const float* cx     = (const float*)d_in[2];
    const float* mem    = (const float*)d_in[3];
    const float* w1     = (const float*)d_in[4];
    const float* b1     = (const float*)d_in[5];
    const float* w2     = (const float*)d_in[6];
    const float* b2     = (const float*)d_in[7];
    const float* w3     = (const float*)d_in[8];
    const float* b3     = (const float*)d_in[9];
    const float* b_out  = (const float*)d_in[10];
    float* out = (float*)d_out;

    static bool attr_set = false;
    if (!attr_set) {
        cudaFuncSetAttribute(hyper_kernel, cudaFuncAttributeMaxDynamicSharedMemorySize, 131072);
        cudaFuncSetAttribute(cell_kernel,  cudaFuncAttributeMaxDynamicSharedMemorySize, 55296);
        attr_set = true;
    }

    hyper_kernel<<<128, 256, 131072>>>(mem, w1, b1, w2, b2, w3, b3);
    cell_kernel<<<512, 512, 55296>>>(inputs, hx, cx, b_out, out);
}

// round 15
// speedup vs baseline: 1.2097x; 1.2097x over previous
#include <cuda_runtime.h>
#include <cuda_bf16.h>
#include <cstdint>

// ---------------------------------------------------------------------------
// DLSTMCell (sm_103 baseline ISA — mma.sync bf16 HMMA path)
//   Kernel 1 (hyper): W_n = mem2_n @ w3 + b3 ->
//     g_Wk[n]: bf16 [256(o', permuted) x 64(k)] SW128-swizzled smem image (32KB)
//     g_Wx[n]: fp32 input-rows i=0,1, stored at permuted columns [2*256]
//   Kernel 2 (cell): per-node D[128,256] = Hbf16[128,64] @ Wk^T via
//     mma.sync.m16n8k16 + fp32 rank-2 input correction + fused LSTM epilogue.
//   Column permutation o' = (ru>>4)*64 + gate*16 + (ru&15) puts all 4 gates of
//   a ru-group into one warp's 64-col stripe -> lane-local LSTM combine.
// ---------------------------------------------------------------------------

#define BATCH 128
#define NNODE 512
#define RUNIT 64
#define HXW   32768          // N*RU
#define W3W   16896

__device__ __align__(16) uint4 g_Wk[NNODE][2048];   // 32KB/node swizzled bf16 image
__device__ float g_Wx[NNODE][512];                  // [n][i*256+o'], i in {0,1}

// ------------------------------ helpers -----------------------------------
__device__ __forceinline__ uint32_t smem_u32(const void* p) {
    uint32_t a;
    asm("{ .reg .u64 t; cvta.to.shared.u64 t, %1; cvt.u32.u64 %0, t; }"
        : "=r"(a) : "l"(p));
    return a;
}
__device__ __forceinline__ uint32_t sw128(uint32_t off) {
    return off ^ ((off >> 3) & 0x70u);
}
__device__ __forceinline__ float tanh_ap(float x) {
    float y; asm("tanh.approx.f32 %0, %1;" : "=f"(y) : "f"(x)); return y;
}
__device__ __forceinline__ float sig_ap(float x) {   // sigmoid via tanh.approx (1 MUFU)
    return fmaf(tanh_ap(0.5f * x), 0.5f, 0.5f);
}
__device__ __forceinline__ uint32_t pack_bf2(float a, float b) {
    __nv_bfloat162 h = __floats2bfloat162_rn(a, b);
    return *reinterpret_cast<uint32_t*>(&h);
}
__device__ __forceinline__ int perm256(int o) {      // gate-interleave permutation
    int g = o >> 6, ru = o & 63;
    return ((ru >> 4) << 6) + (g << 4) + (ru & 15);
}
__device__ __forceinline__ void ldsm4(uint32_t& r0, uint32_t& r1,
                                      uint32_t& r2, uint32_t& r3, uint32_t addr) {
    asm volatile("ldmatrix.sync.aligned.m8n8.x4.shared.b16 {%0,%1,%2,%3}, [%4];"
                 : "=r"(r0), "=r"(r1), "=r"(r2), "=r"(r3) : "r"(addr));
}
__device__ __forceinline__ void mma16816(float* d, const uint32_t* a,
                                         uint32_t b0, uint32_t b1) {
    asm volatile(
        "mma.sync.aligned.m16n8k16.row.col.f32.bf16.bf16.f32 "
        "{%0,%1,%2,%3}, {%4,%5,%6,%7}, {%8,%9}, {%0,%1,%2,%3};"
        : "+f"(d[0]), "+f"(d[1]), "+f"(d[2]), "+f"(d[3])
        : "r"(a[0]), "r"(a[1]), "r"(a[2]), "r"(a[3]), "r"(b0), "r"(b1));
}
__device__ __forceinline__ void cp_async16(uint32_t dst, const void* src) {
    asm volatile("cp.async.cg.shared.global [%0], [%1], 16;"
                 :: "r"(dst), "l"(src) : "memory");
}

// ---------------------------------------------------------------------------
// Kernel 1: hypernetwork. 4 nodes per CTA share the w3/b3 reads.
// grid = 128, block = 512 (k-dim split in 2 groups), dyn smem = 4 * 32KB.
// ---------------------------------------------------------------------------
__global__ void __launch_bounds__(512) hyper_kernel(
    const float* __restrict__ mem, const float* __restrict__ w1,
    const float* __restrict__ b1,  const float* __restrict__ w2,
    const float* __restrict__ b2,  const float* __restrict__ w3,
    const float* __restrict__ b3)
{
    extern __shared__ unsigned char hsm[];   // 4 * 32768 bytes
    __shared__ float s_m1[4][16];
    __shared__ float s_m2[4][4];

    const int t  = threadIdx.x;
    const int n0 = blockIdx.x * 4;
    const uint32_t hbase = smem_u32(hsm);

    if (t < 64) {
        int q = t >> 4, j = t & 15;
        float acc = b1[j];
        #pragma unroll
        for (int k = 0; k < 16; k++)
            acc = fmaf(mem[(n0 + q) * 16 + k], w1[k * 16 + j], acc);
        s_m1[q][j] = tanhf(acc);
    }
    __syncthreads();
    if (t < 16) {
        int q = t >> 2, j = t & 3;
        float acc = b2[j];
        #pragma unroll
        for (int k = 0; k < 16; k++)
            acc = fmaf(s_m1[q][k], w2[k * 4 + j], acc);
        s_m2[q][j] = tanhf(acc);
    }
    __syncthreads();

    float m[4][4];
    #pragma unroll
    for (int q = 0; q < 4; q++)
        #pragma unroll
        for (int mm = 0; mm < 4; mm++) m[q][mm] = s_m2[q][mm];

    const int o  = t & 255;           // original output column 0..255
    const int kg = t >> 8;            // k-group 0..1
    const int op = perm256(o);        // permuted storage column

    // hidden rows i = 2..65 -> bf16 swizzled image, row op (128B), col k
    #pragma unroll 1
    for (int kc = kg * 4; kc < kg * 4 + 4; kc++) {    // 16B chunk = 8 k's
        uint32_t pk[4][4];
        #pragma unroll
        for (int k2 = 0; k2 < 4; k2++) {      // bf16 pairs within chunk
            float v[4][2];
            #pragma unroll
            for (int s = 0; s < 2; s++) {
                int k   = kc * 8 + k2 * 2 + s;
                int idx = (k + 2) * 256 + o;
                float a0 = w3[idx];
                float a1 = w3[W3W + idx];
                float a2 = w3[2 * W3W + idx];
                float a3 = w3[3 * W3W + idx];
                float bb = b3[idx];
                #pragma unroll
                for (int q = 0; q < 4; q++) {
                    float vv = bb;
                    vv = fmaf(m[q][0], a0, vv); vv = fmaf(m[q][1], a1, vv);
                    vv = fmaf(m[q][2], a2, vv); vv = fmaf(m[q][3], a3, vv);
                    v[q][s] = vv;
                }
            }
            #pragma unroll
            for (int q = 0; q < 4; q++) pk[q][k2] = pack_bf2(v[q][0], v[q][1]);
        }
        uint32_t sw = sw128((uint32_t)op * 128u + (uint32_t)kc * 16u);
        #pragma unroll
        for (int q = 0; q < 4; q++)
            asm volatile("st.shared.v4.b32 [%0], {%1, %2, %3, %4};"
                         :: "r"(hbase + q * 32768u + sw),
                            "r"(pk[q][0]), "r"(pk[q][1]), "r"(pk[q][2]), "r"(pk[q][3])
                         : "memory");
    }
    // input rows i = 0..1 -> fp32 g_Wx at permuted column (group 0 only)
    if (kg == 0) {
        #pragma unroll
        for (int i = 0; i < 2; i++) {
            int idx = i * 256 + o;
            float a0 = w3[idx];
            float a1 = w3[W3W + idx];
            float a2 = w3[2 * W3W + idx];
            float a3 = w3[3 * W3W + idx];
            float bb = b3[idx];
            #pragma unroll
            for (int q = 0; q < 4; q++) {
                float v = bb;
                v = fmaf(m[q][0], a0, v); v = fmaf(m[q][1], a1, v);
                v = fmaf(m[q][2], a2, v); v = fmaf(m[q][3], a3, v);
                g_Wx[n0 + q][i * 256 + op] = v;
            }
        }
    }
    __syncthreads();
    // flush swizzled images to gmem (coalesced uint4), 16 per thread
    const uint4* src = (const uint4*)hsm;
    #pragma unroll
    for (int q = 0; q < 4; q++)
        #pragma unroll
        for (int j = 0; j < 4; j++)
            g_Wk[n0 + q][j * 512 + t] = src[q * 2048 + j * 512 + t];
}

// ---------------------------------------------------------------------------
// Kernel 2: per-node HMMA GEMM + LSTM epilogue.
// grid = 512 (one node/CTA), block = 512 (16 warps: mi=w>>2 row-stripe of 32,
// nb=w&3 -> 64 permuted cols = 4 gates x 16 ru). SMEM (1024-aligned base sb):
//   [sb        , +16384) A: 128 x 128B (64 bf16), SW128
//   [sb + 16384, +32768) B: 256 x 128B (64 bf16), SW128 (copied image)
//   [sb + 49152, +2048 ) Wx (512 fp32, permuted cols)
//   [sb + 51200, +1024 ) b_out (256 fp32, permuted)
//   [sb + 52224, +1024 ) XV (x0,x1 per batch row)
// ---------------------------------------------------------------------------
__global__ void __launch_bounds__(512) cell_kernel(
    const float* __restrict__ inputs, const float* __restrict__ hx,
    const float* __restrict__ cx,     const float* __restrict__ b_out,
    float* __restrict__ out)
{
    extern __shared__ unsigned char dsm[];
    const uint32_t raw = smem_u32(dsm);
    const uint32_t sb  = (raw + 1023u) & ~1023u;
    const uint32_t pad = sb - raw;
    const uint32_t A_s = sb;
    const uint32_t B_s = sb + 16384;
    float* WXs = (float*)(dsm + pad + 49152);
    float* BOs = (float*)(dsm + pad + 51200);
    float* XVs = (float*)(dsm + pad + 52224);

    const int n   = blockIdx.x;
    const int tid = threadIdx.x;

    // ---- B tile: async copy of pre-swizzled image (32KB), fire first ----
    {
        const uint4* src = g_Wk[n];
        #pragma unroll
        for (int j = 0; j < 4; j++)
            cp_async16(B_s + (uint32_t)(j * 512 + tid) * 16u, &src[j * 512 + tid]);
        asm volatile("cp.async.commit_group;" ::: "memory");
    }
    // ---- A tile: hx rows -> bf16, SW128. thread: row=tid>>2, quarter=tid&3 ----
    {
        int row = tid >> 2, cq = tid & 3;
        const float4* hp = (const float4*)(hx + (size_t)row * HXW + n * RUNIT + cq * 16);
        float4 p0 = hp[0], p1 = hp[1], p2 = hp[2], p3 = hp[3];
        uint32_t u0 = pack_bf2(p0.x, p0.y), u1 = pack_bf2(p0.z, p0.w);
        uint32_t u2 = pack_bf2(p1.x, p1.y), u3 = pack_bf2(p1.z, p1.w);
        uint32_t u4 = pack_bf2(p2.x, p2.y), u5 = pack_bf2(p2.z, p2.w);
        uint32_t u6 = pack_bf2(p3.x, p3.y), u7 = pack_bf2(p3.z, p3.w);
        uint32_t off = (uint32_t)row * 128u + (uint32_t)cq * 32u;
        asm volatile("st.shared.v4.b32 [%0], {%1, %2, %3, %4};"
                     :: "r"(A_s + sw128(off)), "r"(u0), "r"(u1), "r"(u2), "r"(u3) : "memory");
        asm volatile("st.shared.v4.b32 [%0], {%1, %2, %3, %4};"
                     :: "r"(A_s + sw128(off + 16)), "r"(u4), "r"(u5), "r"(u6), "r"(u7) : "memory");
    }
    // ---- Wx / b_out / x values ----
    WXs[tid] = g_Wx[n][tid];
    if (tid < 256) {
        BOs[perm256(tid)] = b_out[tid];
        XVs[tid] = inputs[(size_t)(tid >> 1) * 1024 + n * 2 + (tid & 1)];
    }
    asm volatile("cp.async.wait_group 0;" ::: "memory");
    __syncthreads();

    // ---- MMA: warp (mi,nb): rows [32mi,32mi+32) x cols [64nb,64nb+64) ----
    const int w  = tid >> 5, l = tid & 31;
    const int mi = w >> 2,  nb = w & 3;

    float acc[2][8][4];
    #pragma unroll
    for (int mt = 0; mt < 2; mt++)
        #pragma unroll
        for (int nt = 0; nt < 8; nt++)
            #pragma unroll
            for (int e = 0; e < 4; e++) acc[mt][nt][e] = 0.0f;

    #pragma unroll
    for (int ks = 0; ks < 4; ks++) {
        uint32_t a[2][4];
        #pragma unroll
        for (int mt = 0; mt < 2; mt++) {
            uint32_t row = (uint32_t)(mi * 32 + mt * 16 + (l & 15));
            uint32_t kc  = (uint32_t)(ks * 2 + (l >> 4));
            ldsm4(a[mt][0], a[mt][1], a[mt][2], a[mt][3],
                  A_s + sw128(row * 128u + kc * 16u));
        }
        uint32_t b[8][2];
        #pragma unroll
        for (int p = 0; p < 4; p++) {
            uint32_t row = (uint32_t)(nb * 64 + p * 16 + (l & 7) + ((l >> 4) << 3));
            uint32_t kc  = (uint32_t)(ks * 2 + ((l >> 3) & 1));
            ldsm4(b[2 * p][0], b[2 * p][1], b[2 * p + 1][0], b[2 * p + 1][1],
                  B_s + sw128(row * 128u + kc * 16u));
        }
        #pragma unroll
        for (int mt = 0; mt < 2; mt++)
            #pragma unroll
            for (int nt = 0; nt < 8; nt++)
                mma16816(acc[mt][nt], a[mt], b[nt][0], b[nt][1]);
    }

    // ---- LSTM epilogue: lane-local gate combine (9 MUFU / element) ----
    const int qrow  = l >> 2;
    const int qc    = (l & 3) << 1;
    const int nbase = n * RUNIT + nb * 16;

    #pragma unroll
    for (int ruhi = 0; ruhi < 2; ruhi++) {
        float wx0[2][4], wx1[2][4], bov[2][4];
        #pragma unroll
        for (int c = 0; c < 2; c++) {
            int o0 = nb * 64 + ruhi * 8 + qc + c;   // permuted col, gate stride 16
            #pragma unroll
            for (int g = 0; g < 4; g++) {
                wx0[c][g] = WXs[o0 + g * 16];
                wx1[c][g] = WXs[256 + o0 + g * 16];
                bov[c][g] = BOs[o0 + g * 16];
            }
        }
        #pragma unroll
        for (int mt = 0; mt < 2; mt++) {
            #pragma unroll
            for (int h = 0; h < 2; h++) {
                int row = mi * 32 + mt * 16 + h * 8 + qrow;
                float x0 = XVs[2 * row], x1 = XVs[2 * row + 1];
                size_t goff = (size_t)row * HXW + nbase + ruhi * 8 + qc;
                float2 cx2 = *(const float2*)(cx + goff);
                float2 hy2, cy2;
                #pragma unroll
                for (int c = 0; c < 2; c++) {
                    int e = h * 2 + c;
                    float li = fmaf(x1, wx1[c][0], fmaf(x0, wx0[c][0], acc[mt][0 + ruhi][e]));
                    float lf = fmaf(x1, wx1[c][1], fmaf(x0, wx0[c][1], acc[mt][2 + ruhi][e]));
                    float lg = fmaf(x1, wx1[c][2], fmaf(x0, wx0[c][2], acc[mt][4 + ruhi][e]));
                    float lo = fmaf(x1, wx1[c][3], fmaf(x0, wx0[c][3], acc[mt][6 + ruhi][e]));
                    float vi = sig_ap(li) + bov[c][0];
                    float vf = sig_ap(lf) + bov[c][1];
                    float vg = sig_ap(lg) + bov[c][2];
                    float vo = sig_ap(lo) + bov[c][3];
                    float it = sig_ap(vi);
                    float ft = sig_ap(vf);
                    float gt = tanh_ap(vg);
                    float ot = sig_ap(vo);
                    float cxv = c ? cx2.y : cx2.x;
                    float cc = fmaf(cxv, ft, it * gt);
                    float hh = ot * tanh_ap(cc);
                    if (c == 0) { cy2.x = cc; hy2.x = hh; }
                    else        { cy2.y = cc; hy2.y = hh; }
                }
                *(float2*)(out + goff) = hy2;
                *(float2*)(out + (size_t)BATCH * HXW + goff) = cy2;
            }
        }
    }
}

// ---------------------------------------------------------------------------
extern "C" void kernel_launch(void* const* d_in, const int* in_sizes, int n_in,
                              void* d_out, int out_size)
{
    (void)in_sizes; (void)n_in; (void)out_size;
    const float* inputs = (const float*)d_in[0];
    const float* hx     = (const float*)d_in[1];
    const float* cx     = (const float*)d_in[2];
    const float* mem    = (const float*)d_in[3];
    const float* w1     = (const float*)d_in[4];
    const float* b1     = (const float*)d_in[5];
    const float* w2     = (const float*)d_in[6];
    const float* b2     = (const float*)d_in[7];
    const float* w3     = (const float*)d_in[8];
    const float* b3     = (const float*)d_in[9];
    const float* b_out  = (const float*)d_in[10];
    float* out = (float*)d_out;

    static bool attr_set = false;
    if (!attr_set) {
        cudaFuncSetAttribute(hyper_kernel, cudaFuncAttributeMaxDynamicSharedMemorySize, 131072);
        cudaFuncSetAttribute(cell_kernel,  cudaFuncAttributeMaxDynamicSharedMemorySize, 55296);
        attr_set = true;
    }

    hyper_kernel<<<128, 512, 131072>>>(mem, w1, b1, w2, b2, w3, b3);
    cell_kernel<<<512, 512, 55296>>>(inputs, hx, cx, b_out, out);
}